// round 3
// baseline (speedup 1.0000x reference)
#include <cuda_runtime.h>
#include <math.h>

// Problem constants
#define S_ 128
#define B_ 64
#define V_ 10000
#define E_ 256
#define H_ 512

// Recurrence kernel config
#define NB 128          // persistent CTAs (all co-resident: 1 CTA/SM, 128 <= 148 SMs)
#define TPB 256
#define KC 128          // K-chunk staged in smem

// ---------------- device scratch (static, allocation-free) ----------------
__device__ float g_h0T[2][H_ * B_];      // hidden layer0, transposed [k][b], ping-pong
__device__ float g_h1T[2][H_ * B_];
__device__ float g_r0T[H_ * B_];
__device__ float g_r1T[H_ * B_];
__device__ float g_Xp[3u * S_ * H_ * B_];    // precomputed x-projections [g][t][n][b]
__device__ float g_H1[(size_t)S_ * B_ * H_]; // h1 for all steps, row-major [t*B+b][k]
__device__ unsigned g_bar_count = 0;
__device__ unsigned g_bar_gen = 0;

// ---------------- grid barrier (generation counter, hang-free while co-resident) ----
__device__ __forceinline__ void grid_barrier() {
    __syncthreads();
    if (threadIdx.x == 0) {
        __threadfence();
        unsigned gen = *((volatile unsigned*)&g_bar_gen);
        unsigned ticket = atomicAdd(&g_bar_count, 1u);
        if (ticket == NB - 1) {
            g_bar_count = 0;
            __threadfence();
            atomicAdd(&g_bar_gen, 1u);
        } else {
            while (*((volatile unsigned*)&g_bar_gen) == gen) { __nanosleep(64); }
        }
        __threadfence();
    }
    __syncthreads();
}

__device__ __forceinline__ float sigmoidf_(float x) { return 1.0f / (1.0f + expf(-x)); }

// ---------------- smem staging helpers ----------------
__device__ __forceinline__ void stage(float* __restrict__ sA, const float* __restrict__ src) {
    float4* d = (float4*)sA;
    const float4* s = (const float4*)src;
    for (int j = threadIdx.x; j < (KC * B_) / 4; j += TPB) d[j] = s[j];
}
__device__ __forceinline__ void stage_mul(float* __restrict__ sA, const float* __restrict__ src,
                                          const float* __restrict__ rsrc) {
    float4* d = (float4*)sA;
    const float4* s = (const float4*)src;
    const float4* r = (const float4*)rsrc;
    for (int j = threadIdx.x; j < (KC * B_) / 4; j += TPB) {
        float4 a = s[j]; float4 rr = r[j];
        d[j] = make_float4(a.x * rr.x, a.y * rr.y, a.z * rr.z, a.w * rr.w);
    }
}

// ---------------- per-chunk dot helpers (weights + A both in smem) ----------------
__device__ __forceinline__ void mm2(const float* __restrict__ sWa, const float* __restrict__ sWb,
                                    const float* __restrict__ sA, int b, float& acca, float& accb) {
    #pragma unroll
    for (int kk = 0; kk < KC; kk += 4) {
        float4 wa = *(const float4*)(sWa + kk);
        float4 wb = *(const float4*)(sWb + kk);
        float a0 = sA[(kk + 0) * B_ + b];
        float a1 = sA[(kk + 1) * B_ + b];
        float a2 = sA[(kk + 2) * B_ + b];
        float a3 = sA[(kk + 3) * B_ + b];
        acca = fmaf(a0, wa.x, acca); acca = fmaf(a1, wa.y, acca);
        acca = fmaf(a2, wa.z, acca); acca = fmaf(a3, wa.w, acca);
        accb = fmaf(a0, wb.x, accb); accb = fmaf(a1, wb.y, accb);
        accb = fmaf(a2, wb.z, accb); accb = fmaf(a3, wb.w, accb);
    }
}
__device__ __forceinline__ void mm1(const float* __restrict__ sW, const float* __restrict__ sA,
                                    int b, float& acc) {
    #pragma unroll
    for (int kk = 0; kk < KC; kk += 4) {
        float4 w = *(const float4*)(sW + kk);
        float a0 = sA[(kk + 0) * B_ + b];
        float a1 = sA[(kk + 1) * B_ + b];
        float a2 = sA[(kk + 2) * B_ + b];
        float a3 = sA[(kk + 3) * B_ + b];
        acc = fmaf(a0, w.x, acc); acc = fmaf(a1, w.y, acc);
        acc = fmaf(a2, w.z, acc); acc = fmaf(a3, w.w, acc);
    }
}

// ---------------- smem layout for recurrence (floats) ----------------
#define SM_WR0 0
#define SM_WZ0 2048
#define SM_WH0 4096
#define SM_WR1 6144
#define SM_WZ1 10240
#define SM_WH1 14336
#define SM_A   18432
#define SM_FLOATS (18432 + KC * B_)
#define SMEM_BYTES (SM_FLOATS * 4)

// ---------------- init / finalize ----------------
__global__ void init_hidden_kernel(const float* __restrict__ hidden) {
    int i = blockIdx.x * blockDim.x + threadIdx.x;
    if (i < B_ * H_) {
        int b = i / H_, k = i % H_;
        g_h0T[0][k * B_ + b] = hidden[0 * B_ * H_ + i];
        g_h1T[0][k * B_ + b] = hidden[1 * B_ * H_ + i];
    }
}
__global__ void write_hidden_kernel(float* __restrict__ out, long long off) {
    int i = blockIdx.x * blockDim.x + threadIdx.x;
    if (i < B_ * H_) {
        int b = i / H_, k = i % H_;
        out[off + i] = g_h0T[0][k * B_ + b];              // S even -> final parity 0
        out[off + B_ * H_ + i] = g_h1T[0][k * B_ + b];
    }
}

// ---------------- xproj GEMM: Xp_g = emb(tok) @ Wg0[:,H:]^T + bg0 ----------------
// grid: (12 n-tiles of 128, 64 m-tiles of 128). N = 3*512 = 1536, K = 256.
__global__ void xproj_gemm(const int* __restrict__ tok, const float* __restrict__ emb,
                           const float* __restrict__ Wr0, const float* __restrict__ Wz0,
                           const float* __restrict__ Wh0,
                           const float* __restrict__ br0, const float* __restrict__ bz0,
                           const float* __restrict__ bh0) {
    __shared__ float As[16][128];
    __shared__ float Bs[16][128];
    __shared__ int stok[128];
    int n0 = blockIdx.x * 128;
    int m0 = blockIdx.y * 128;
    int g = n0 / H_;
    int nb = n0 % H_;
    const float* W = (g == 0) ? Wr0 : (g == 1) ? Wz0 : Wh0;
    const float* bias = (g == 0) ? br0 : (g == 1) ? bz0 : bh0;
    int tid = threadIdx.x;
    if (tid < 128) stok[tid] = tok[m0 + tid];
    __syncthreads();
    int tx = tid % 16, ty = tid / 16;
    float acc[8][8];
    #pragma unroll
    for (int i = 0; i < 8; i++)
        #pragma unroll
        for (int j = 0; j < 8; j++) acc[i][j] = 0.f;

    for (int k0 = 0; k0 < E_; k0 += 16) {
        #pragma unroll
        for (int r = 0; r < 2; r++) {
            int f = tid + r * 256;
            int row = f >> 2, q = f & 3;
            int t = stok[row];
            float4 v = *(const float4*)&emb[(size_t)t * E_ + k0 + q * 4];
            As[q * 4 + 0][row] = v.x; As[q * 4 + 1][row] = v.y;
            As[q * 4 + 2][row] = v.z; As[q * 4 + 3][row] = v.w;
        }
        #pragma unroll
        for (int r = 0; r < 2; r++) {
            int f = tid + r * 256;
            int row = f >> 2, q = f & 3;
            float4 v = *(const float4*)&W[(size_t)(nb + row) * (H_ + E_) + H_ + k0 + q * 4];
            Bs[q * 4 + 0][row] = v.x; Bs[q * 4 + 1][row] = v.y;
            Bs[q * 4 + 2][row] = v.z; Bs[q * 4 + 3][row] = v.w;
        }
        __syncthreads();
        #pragma unroll
        for (int kk = 0; kk < 16; kk++) {
            float a[8], bv[8];
            *(float4*)&a[0] = *(const float4*)&As[kk][ty * 8];
            *(float4*)&a[4] = *(const float4*)&As[kk][ty * 8 + 4];
            *(float4*)&bv[0] = *(const float4*)&Bs[kk][tx * 8];
            *(float4*)&bv[4] = *(const float4*)&Bs[kk][tx * 8 + 4];
            #pragma unroll
            for (int i = 0; i < 8; i++)
                #pragma unroll
                for (int j = 0; j < 8; j++) acc[i][j] = fmaf(a[i], bv[j], acc[i][j]);
        }
        __syncthreads();
    }
    float bfrag[8];
    *(float4*)&bfrag[0] = *(const float4*)&bias[nb + tx * 8];
    *(float4*)&bfrag[4] = *(const float4*)&bias[nb + tx * 8 + 4];
    float* Xg = g_Xp + (size_t)g * S_ * H_ * B_;
    #pragma unroll
    for (int i = 0; i < 8; i++) {
        int row = m0 + ty * 8 + i;
        int t = row >> 6, b = row & 63;
        #pragma unroll
        for (int j = 0; j < 8; j++) {
            int n = nb + tx * 8 + j;
            Xg[((size_t)t * H_ + n) * B_ + b] = acc[i][j] + bfrag[j];
        }
    }
}

// ---------------- persistent recurrence kernel ----------------
// CTA c owns columns n in [c*4, c*4+4). thread -> (b = tid%64, cg = tid/64).
__global__ void __launch_bounds__(TPB)
recurrence_kernel(const float* __restrict__ Wr0, const float* __restrict__ Wz0,
                  const float* __restrict__ Wh0,
                  const float* __restrict__ Wr1, const float* __restrict__ Wz1,
                  const float* __restrict__ Wh1,
                  const float* __restrict__ br1, const float* __restrict__ bz1,
                  const float* __restrict__ bh1) {
    extern __shared__ float sm[];
    float* sWr0 = sm + SM_WR0;
    float* sWz0 = sm + SM_WZ0;
    float* sWh0 = sm + SM_WH0;
    float* sWr1 = sm + SM_WR1;
    float* sWz1 = sm + SM_WZ1;
    float* sWh1 = sm + SM_WH1;
    float* sA   = sm + SM_A;

    int c = blockIdx.x;
    int n0 = c * 4;
    int tid = threadIdx.x;
    int b = tid % B_;
    int cg = tid / B_;           // 0..3
    int n = n0 + cg;

    // Preload this CTA's weight columns (layer0: h-part only; layer1: full 1024)
    for (int j = tid; j < 4 * H_ / 4; j += TPB) {         // 512 float4
        int g = j / (H_ / 4), k4 = j % (H_ / 4);
        ((float4*)sWr0)[j] = *(const float4*)&Wr0[(size_t)(n0 + g) * (H_ + E_) + k4 * 4];
        ((float4*)sWz0)[j] = *(const float4*)&Wz0[(size_t)(n0 + g) * (H_ + E_) + k4 * 4];
        ((float4*)sWh0)[j] = *(const float4*)&Wh0[(size_t)(n0 + g) * (H_ + E_) + k4 * 4];
    }
    for (int j = tid; j < 4 * 1024 / 4; j += TPB) {       // 1024 float4
        int g = j / 256, k4 = j % 256;
        ((float4*)sWr1)[j] = *(const float4*)&Wr1[(size_t)(n0 + g) * 1024 + k4 * 4];
        ((float4*)sWz1)[j] = *(const float4*)&Wz1[(size_t)(n0 + g) * 1024 + k4 * 4];
        ((float4*)sWh1)[j] = *(const float4*)&Wh1[(size_t)(n0 + g) * 1024 + k4 * 4];
    }
    float vbr1 = br1[n], vbz1 = bz1[n], vbh1 = bh1[n];
    grid_barrier();   // orders weight preload + init_hidden vs compute

    for (int t = 0; t < S_; ++t) {
        int cur = t & 1, nxt = cur ^ 1;
        const float* h0c = g_h0T[cur];
        float* h0n = g_h0T[nxt];
        const float* h1c = g_h1T[cur];
        float* h1n = g_h1T[nxt];

        // ---- P1: r0, z0 ----
        float accr = g_Xp[0 * (size_t)S_ * H_ * B_ + ((size_t)t * H_ + n) * B_ + b];
        float accz = g_Xp[1 * (size_t)S_ * H_ * B_ + ((size_t)t * H_ + n) * B_ + b];
        for (int kc = 0; kc < H_; kc += KC) {
            stage(sA, h0c + kc * B_);
            __syncthreads();
            mm2(sWr0 + cg * H_ + kc, sWz0 + cg * H_ + kc, sA, b, accr, accz);
            __syncthreads();
        }
        float r0 = sigmoidf_(accr);
        float z0 = sigmoidf_(accz);
        g_r0T[n * B_ + b] = r0;
        grid_barrier();

        // ---- P2: h~0, h0 update ----
        float acch = g_Xp[2 * (size_t)S_ * H_ * B_ + ((size_t)t * H_ + n) * B_ + b];
        for (int kc = 0; kc < H_; kc += KC) {
            stage_mul(sA, h0c + kc * B_, g_r0T + kc * B_);
            __syncthreads();
            mm1(sWh0 + cg * H_ + kc, sA, b, acch);
            __syncthreads();
        }
        float ht0 = tanhf(acch);
        float h0old = h0c[n * B_ + b];
        float h0new = (1.f - z0) * h0old + z0 * ht0;
        h0n[n * B_ + b] = h0new;
        grid_barrier();

        // ---- P3: r1, z1 over comb = [h1, h0new], K = 1024 ----
        accr = vbr1; accz = vbz1;
        for (int kc = 0; kc < 1024; kc += KC) {
            const float* src = (kc < H_) ? (h1c + kc * B_) : (h0n + (kc - H_) * B_);
            stage(sA, src);
            __syncthreads();
            mm2(sWr1 + cg * 1024 + kc, sWz1 + cg * 1024 + kc, sA, b, accr, accz);
            __syncthreads();
        }
        float r1 = sigmoidf_(accr);
        float z1 = sigmoidf_(accz);
        g_r1T[n * B_ + b] = r1;
        grid_barrier();

        // ---- P4: h~1, h1 update ----
        // NOTE: no grid barrier after P4. h1n / g_H1 written here are first read
        // in next step's P3, and the P1+P2 barriers of the next step stand in
        // between. Racing CTAs in next P1/P2 write only r0T / h0T[cur] which no
        // lagging P4 CTA touches.
        acch = vbh1;
        for (int kc = 0; kc < 1024; kc += KC) {
            if (kc < H_) stage_mul(sA, h1c + kc * B_, g_r1T + kc * B_);
            else         stage(sA, h0n + (kc - H_) * B_);
            __syncthreads();
            mm1(sWh1 + cg * 1024 + kc, sA, b, acch);
            __syncthreads();
        }
        float ht1 = tanhf(acch);
        float h1old = h1c[n * B_ + b];
        float h1new = (1.f - z1) * h1old + z1 * ht1;
        h1n[n * B_ + b] = h1new;
        g_H1[((size_t)t * B_ + b) * H_ + n] = h1new;
    }
}

// ---------------- output GEMM: logits = H1 @ Wy^T + by ----------------
// M = 8192, N = 10000 (padded tiles), K = 512. grid (79, 64).
__global__ void out_gemm(const float* __restrict__ Wy, const float* __restrict__ by,
                         float* __restrict__ out) {
    __shared__ float As[16][128];
    __shared__ float Bs[16][128];
    int n0 = blockIdx.x * 128;
    int m0 = blockIdx.y * 128;
    int tid = threadIdx.x;
    int tx = tid % 16, ty = tid / 16;
    float acc[8][8];
    #pragma unroll
    for (int i = 0; i < 8; i++)
        #pragma unroll
        for (int j = 0; j < 8; j++) acc[i][j] = 0.f;

    const float* A = g_H1;
    for (int k0 = 0; k0 < H_; k0 += 16) {
        #pragma unroll
        for (int r = 0; r < 2; r++) {
            int f = tid + r * 256;
            int row = f >> 2, q = f & 3;
            float4 v = *(const float4*)&A[(size_t)(m0 + row) * H_ + k0 + q * 4];
            As[q * 4 + 0][row] = v.x; As[q * 4 + 1][row] = v.y;
            As[q * 4 + 2][row] = v.z; As[q * 4 + 3][row] = v.w;
        }
        #pragma unroll
        for (int r = 0; r < 2; r++) {
            int f = tid + r * 256;
            int row = f >> 2, q = f & 3;
            int nn = n0 + row;
            float4 v = make_float4(0.f, 0.f, 0.f, 0.f);
            if (nn < V_) v = *(const float4*)&Wy[(size_t)nn * H_ + k0 + q * 4];
            Bs[q * 4 + 0][row] = v.x; Bs[q * 4 + 1][row] = v.y;
            Bs[q * 4 + 2][row] = v.z; Bs[q * 4 + 3][row] = v.w;
        }
        __syncthreads();
        #pragma unroll
        for (int kk = 0; kk < 16; kk++) {
            float a[8], bv[8];
            *(float4*)&a[0] = *(const float4*)&As[kk][ty * 8];
            *(float4*)&a[4] = *(const float4*)&As[kk][ty * 8 + 4];
            *(float4*)&bv[0] = *(const float4*)&Bs[kk][tx * 8];
            *(float4*)&bv[4] = *(const float4*)&Bs[kk][tx * 8 + 4];
            #pragma unroll
            for (int i = 0; i < 8; i++)
                #pragma unroll
                for (int j = 0; j < 8; j++) acc[i][j] = fmaf(a[i], bv[j], acc[i][j]);
        }
        __syncthreads();
    }
    #pragma unroll
    for (int i = 0; i < 8; i++) {
        size_t row = (size_t)m0 + ty * 8 + i;
        #pragma unroll
        for (int j = 0; j < 8; j++) {
            int v = n0 + tx * 8 + j;
            if (v < V_) out[row * V_ + v] = acc[i][j] + by[v];
        }
    }
}

// ---------------- launch ----------------
extern "C" void kernel_launch(void* const* d_in, const int* in_sizes, int n_in,
                              void* d_out, int out_size) {
    const int*   inputs = (const int*)d_in[0];
    const float* hidden = (const float*)d_in[1];
    const float* emb    = (const float*)d_in[2];
    const float* W_r0 = (const float*)d_in[3];
    const float* b_r0 = (const float*)d_in[4];
    const float* W_z0 = (const float*)d_in[5];
    const float* b_z0 = (const float*)d_in[6];
    const float* W_h0 = (const float*)d_in[7];
    const float* b_h0 = (const float*)d_in[8];
    const float* W_r1 = (const float*)d_in[9];
    const float* b_r1 = (const float*)d_in[10];
    const float* W_z1 = (const float*)d_in[11];
    const float* b_z1 = (const float*)d_in[12];
    const float* W_h1 = (const float*)d_in[13];
    const float* b_h1 = (const float*)d_in[14];
    const float* Wy   = (const float*)d_in[15];
    const float* by   = (const float*)d_in[16];
    float* out = (float*)d_out;

    cudaFuncSetAttribute(recurrence_kernel, cudaFuncAttributeMaxDynamicSharedMemorySize,
                         SMEM_BYTES);

    xproj_gemm<<<dim3(3 * H_ / 128, (S_ * B_) / 128), 256>>>(inputs, emb, W_r0, W_z0, W_h0,
                                                             b_r0, b_z0, b_h0);
    init_hidden_kernel<<<(B_ * H_ + 255) / 256, 256>>>(hidden);
    recurrence_kernel<<<NB, TPB, SMEM_BYTES>>>(W_r0, W_z0, W_h0, W_r1, W_z1, W_h1,
                                               b_r1, b_z1, b_h1);
    out_gemm<<<dim3((V_ + 127) / 128, (S_ * B_) / 128), 256>>>(Wy, by, out);

    long long logits_elems = (long long)S_ * B_ * V_;
    if ((long long)out_size >= logits_elems + 2LL * B_ * H_) {
        write_hidden_kernel<<<(B_ * H_ + 255) / 256, 256>>>(out, logits_elems);
    }
}

// round 4
// speedup vs baseline: 1.0288x; 1.0288x over previous
#include <cuda_runtime.h>
#include <math.h>

// Problem constants
#define S_ 128
#define B_ 64
#define V_ 10000
#define E_ 256
#define H_ 512

// Recurrence kernel config
#define NB 128          // persistent CTAs (all co-resident: 1 CTA/SM, 128 <= 148 SMs)
#define TPB 256
#define KC 256          // K-chunk staged in smem

// ---------------- device scratch (static, allocation-free) ----------------
__device__ float g_h0T[2][H_ * B_];      // hidden layer0, transposed [k][b], ping-pong
__device__ float g_h1T[2][H_ * B_];
__device__ float g_r0T[H_ * B_];
__device__ float g_r1T[H_ * B_];
__device__ float g_Xp[3u * S_ * H_ * B_];    // precomputed x-projections [g][t][n][b]
__device__ float g_H1[(size_t)S_ * B_ * H_]; // h1 for all steps, row-major [t*B+b][k]
__device__ unsigned g_bar_count = 0;
__device__ unsigned g_bar_gen = 0;

// ---------------- packed f32x2 helpers ----------------
__device__ __forceinline__ void fma2(unsigned long long& acc, unsigned long long a,
                                     unsigned long long w) {
    asm("fma.rn.f32x2 %0, %1, %2, %0;" : "+l"(acc) : "l"(a), "l"(w));
}
__device__ __forceinline__ float unpack_sum(unsigned long long v) {
    return __uint_as_float((unsigned)v) + __uint_as_float((unsigned)(v >> 32));
}
__device__ __forceinline__ unsigned long long dup2(float f) {
    unsigned long long d;
    asm("mov.b64 %0, {%1, %1};" : "=l"(d) : "r"(__float_as_uint(f)));
    return d;
}

// ---------------- grid barrier ----------------
__device__ __forceinline__ void grid_barrier() {
    __syncthreads();
    if (threadIdx.x == 0) {
        __threadfence();
        unsigned gen = *((volatile unsigned*)&g_bar_gen);
        unsigned ticket = atomicAdd(&g_bar_count, 1u);
        if (ticket == NB - 1) {
            g_bar_count = 0;
            __threadfence();
            atomicAdd(&g_bar_gen, 1u);
        } else {
            while (*((volatile unsigned*)&g_bar_gen) == gen) { __nanosleep(64); }
        }
        __threadfence();
    }
    __syncthreads();
}

__device__ __forceinline__ float sigmoidf_(float x) { return 1.0f / (1.0f + expf(-x)); }

// ---------------- smem layout (floats) ----------------
// Weight rows padded: layer0 row = 516 (=512+4), layer1 row = 1028 (=1024+4).
// A tile: [b][k] with row stride 260 (=256+4).
#define W0ROW 516
#define W1ROW 1028
#define SAROW 260
#define SM_WR0 0
#define SM_WZ0 (SM_WR0 + 4 * W0ROW)          // 2064
#define SM_WH0 (SM_WZ0 + 4 * W0ROW)          // 4128
#define SM_WR1 (SM_WH0 + 4 * W0ROW)          // 6192
#define SM_WZ1 (SM_WR1 + 4 * W1ROW)          // 10304
#define SM_WH1 (SM_WZ1 + 4 * W1ROW)          // 14416
#define SM_A   (SM_WH1 + 4 * W1ROW)          // 18528
#define SM_FLOATS (SM_A + B_ * SAROW)        // 18528 + 16640 = 35168
#define SMEM_BYTES (SM_FLOATS * 4)           // 140672

// ---------------- staging: global [k][b] -> smem [b][k] (transposed, padded) ------
// thread: b = tid&63, kq = tid>>6 covers 64 k. Conflict-free STS.128.
__device__ __forceinline__ void stageT(float* __restrict__ sA, const float* __restrict__ src) {
    int b = threadIdx.x & 63;
    int kq = threadIdx.x >> 6;
    #pragma unroll
    for (int g = 0; g < 16; g++) {
        int k = kq * 64 + g * 4;
        float a0 = src[(k + 0) * B_ + b];
        float a1 = src[(k + 1) * B_ + b];
        float a2 = src[(k + 2) * B_ + b];
        float a3 = src[(k + 3) * B_ + b];
        *(float4*)(sA + b * SAROW + k) = make_float4(a0, a1, a2, a3);
    }
}
__device__ __forceinline__ void stageT_mul(float* __restrict__ sA, const float* __restrict__ src,
                                           const float* __restrict__ rsrc) {
    int b = threadIdx.x & 63;
    int kq = threadIdx.x >> 6;
    #pragma unroll
    for (int g = 0; g < 16; g++) {
        int k = kq * 64 + g * 4;
        float a0 = src[(k + 0) * B_ + b] * rsrc[(k + 0) * B_ + b];
        float a1 = src[(k + 1) * B_ + b] * rsrc[(k + 1) * B_ + b];
        float a2 = src[(k + 2) * B_ + b] * rsrc[(k + 2) * B_ + b];
        float a3 = src[(k + 3) * B_ + b] * rsrc[(k + 3) * B_ + b];
        *(float4*)(sA + b * SAROW + k) = make_float4(a0, a1, a2, a3);
    }
}

// ---------------- chunk dot products (f32x2, multi-chain) ----------------
__device__ __forceinline__ void mm2_chunk(const float* __restrict__ wA, const float* __restrict__ wB,
                                          const float* __restrict__ aRow,
                                          unsigned long long& pa0, unsigned long long& pa1,
                                          unsigned long long& pb0, unsigned long long& pb1) {
    #pragma unroll 16
    for (int kk = 0; kk < KC; kk += 4) {
        ulonglong2 av = *(const ulonglong2*)(aRow + kk);
        ulonglong2 wa = *(const ulonglong2*)(wA + kk);
        ulonglong2 wb = *(const ulonglong2*)(wB + kk);
        fma2(pa0, av.x, wa.x); fma2(pa1, av.y, wa.y);
        fma2(pb0, av.x, wb.x); fma2(pb1, av.y, wb.y);
    }
}
__device__ __forceinline__ void mm1_chunk(const float* __restrict__ wA,
                                          const float* __restrict__ aRow,
                                          unsigned long long& p0, unsigned long long& p1,
                                          unsigned long long& p2, unsigned long long& p3) {
    #pragma unroll 8
    for (int kk = 0; kk < KC; kk += 8) {
        ulonglong2 av0 = *(const ulonglong2*)(aRow + kk);
        ulonglong2 av1 = *(const ulonglong2*)(aRow + kk + 4);
        ulonglong2 wa0 = *(const ulonglong2*)(wA + kk);
        ulonglong2 wa1 = *(const ulonglong2*)(wA + kk + 4);
        fma2(p0, av0.x, wa0.x); fma2(p1, av0.y, wa0.y);
        fma2(p2, av1.x, wa1.x); fma2(p3, av1.y, wa1.y);
    }
}

// ---------------- init / finalize ----------------
__global__ void init_hidden_kernel(const float* __restrict__ hidden) {
    int i = blockIdx.x * blockDim.x + threadIdx.x;
    if (i < B_ * H_) {
        int b = i / H_, k = i % H_;
        g_h0T[0][k * B_ + b] = hidden[0 * B_ * H_ + i];
        g_h1T[0][k * B_ + b] = hidden[1 * B_ * H_ + i];
    }
}
__global__ void write_hidden_kernel(float* __restrict__ out, long long off) {
    int i = blockIdx.x * blockDim.x + threadIdx.x;
    if (i < B_ * H_) {
        int b = i / H_, k = i % H_;
        out[off + i] = g_h0T[0][k * B_ + b];              // S even -> final parity 0
        out[off + B_ * H_ + i] = g_h1T[0][k * B_ + b];
    }
}

// ---------------- xproj GEMM: Xp_g = emb(tok) @ Wg0[:,H:]^T + bg0 ----------------
__global__ void xproj_gemm(const int* __restrict__ tok, const float* __restrict__ emb,
                           const float* __restrict__ Wr0, const float* __restrict__ Wz0,
                           const float* __restrict__ Wh0,
                           const float* __restrict__ br0, const float* __restrict__ bz0,
                           const float* __restrict__ bh0) {
    __shared__ float As[16][128];
    __shared__ float Bs[16][128];
    __shared__ int stok[128];
    int n0 = blockIdx.x * 128;
    int m0 = blockIdx.y * 128;
    int g = n0 / H_;
    int nb = n0 % H_;
    const float* W = (g == 0) ? Wr0 : (g == 1) ? Wz0 : Wh0;
    const float* bias = (g == 0) ? br0 : (g == 1) ? bz0 : bh0;
    int tid = threadIdx.x;
    if (tid < 128) stok[tid] = tok[m0 + tid];
    __syncthreads();
    int tx = tid % 16, ty = tid / 16;
    float acc[8][8];
    #pragma unroll
    for (int i = 0; i < 8; i++)
        #pragma unroll
        for (int j = 0; j < 8; j++) acc[i][j] = 0.f;

    for (int k0 = 0; k0 < E_; k0 += 16) {
        #pragma unroll
        for (int r = 0; r < 2; r++) {
            int f = tid + r * 256;
            int row = f >> 2, q = f & 3;
            int t = stok[row];
            float4 v = *(const float4*)&emb[(size_t)t * E_ + k0 + q * 4];
            As[q * 4 + 0][row] = v.x; As[q * 4 + 1][row] = v.y;
            As[q * 4 + 2][row] = v.z; As[q * 4 + 3][row] = v.w;
        }
        #pragma unroll
        for (int r = 0; r < 2; r++) {
            int f = tid + r * 256;
            int row = f >> 2, q = f & 3;
            float4 v = *(const float4*)&W[(size_t)(nb + row) * (H_ + E_) + H_ + k0 + q * 4];
            Bs[q * 4 + 0][row] = v.x; Bs[q * 4 + 1][row] = v.y;
            Bs[q * 4 + 2][row] = v.z; Bs[q * 4 + 3][row] = v.w;
        }
        __syncthreads();
        #pragma unroll
        for (int kk = 0; kk < 16; kk++) {
            float a[8], bv[8];
            *(float4*)&a[0] = *(const float4*)&As[kk][ty * 8];
            *(float4*)&a[4] = *(const float4*)&As[kk][ty * 8 + 4];
            *(float4*)&bv[0] = *(const float4*)&Bs[kk][tx * 8];
            *(float4*)&bv[4] = *(const float4*)&Bs[kk][tx * 8 + 4];
            #pragma unroll
            for (int i = 0; i < 8; i++)
                #pragma unroll
                for (int j = 0; j < 8; j++) acc[i][j] = fmaf(a[i], bv[j], acc[i][j]);
        }
        __syncthreads();
    }
    float bfrag[8];
    *(float4*)&bfrag[0] = *(const float4*)&bias[nb + tx * 8];
    *(float4*)&bfrag[4] = *(const float4*)&bias[nb + tx * 8 + 4];
    float* Xg = g_Xp + (size_t)g * S_ * H_ * B_;
    #pragma unroll
    for (int i = 0; i < 8; i++) {
        int row = m0 + ty * 8 + i;
        int t = row >> 6, b = row & 63;
        #pragma unroll
        for (int j = 0; j < 8; j++) {
            int n = nb + tx * 8 + j;
            Xg[((size_t)t * H_ + n) * B_ + b] = acc[i][j] + bfrag[j];
        }
    }
}

// ---------------- persistent recurrence kernel ----------------
// CTA c owns columns n0..n0+3. thread -> (b = tid>>2, cg = tid&3).
// Warp = 8 distinct b x 4 cg: A-loads multicast (8 addrs), W-loads multicast (4 addrs).
__global__ void __launch_bounds__(TPB)
recurrence_kernel(const float* __restrict__ Wr0, const float* __restrict__ Wz0,
                  const float* __restrict__ Wh0,
                  const float* __restrict__ Wr1, const float* __restrict__ Wz1,
                  const float* __restrict__ Wh1,
                  const float* __restrict__ br1, const float* __restrict__ bz1,
                  const float* __restrict__ bh1) {
    extern __shared__ float sm[];
    float* sWr0 = sm + SM_WR0;
    float* sWz0 = sm + SM_WZ0;
    float* sWh0 = sm + SM_WH0;
    float* sWr1 = sm + SM_WR1;
    float* sWz1 = sm + SM_WZ1;
    float* sWh1 = sm + SM_WH1;
    float* sA   = sm + SM_A;

    int c = blockIdx.x;
    int n0 = c * 4;
    int tid = threadIdx.x;
    int cg = tid & 3;
    int b = tid >> 2;            // 0..63
    int n = n0 + cg;

    // Preload weights into padded smem rows.
    // Layer0 (h-part, K=512): 3 gates x 4 rows x 128 float4 = 1536 float4.
    for (int j = tid; j < 1536; j += TPB) {
        int g = j >> 9;                   // 0..2
        int r = (j >> 7) & 3;             // row
        int k4 = j & 127;
        const float* Wsrc = (g == 0) ? Wr0 : (g == 1) ? Wz0 : Wh0;
        float* Wdst = (g == 0) ? sWr0 : (g == 1) ? sWz0 : sWh0;
        *(float4*)(Wdst + r * W0ROW + k4 * 4) =
            *(const float4*)&Wsrc[(size_t)(n0 + r) * (H_ + E_) + k4 * 4];
    }
    // Layer1 (K=1024): 3 gates x 4 rows x 256 float4 = 3072 float4.
    for (int j = tid; j < 3072; j += TPB) {
        int g = j >> 10;
        int r = (j >> 8) & 3;
        int k4 = j & 255;
        const float* Wsrc = (g == 0) ? Wr1 : (g == 1) ? Wz1 : Wh1;
        float* Wdst = (g == 0) ? sWr1 : (g == 1) ? sWz1 : sWh1;
        *(float4*)(Wdst + r * W1ROW + k4 * 4) =
            *(const float4*)&Wsrc[(size_t)(n0 + r) * 1024 + k4 * 4];
    }
    float vbr1 = br1[n], vbz1 = bz1[n], vbh1 = bh1[n];
    grid_barrier();   // orders weight preload + init_hidden vs compute

    const float* aRow = sA + b * SAROW;

    for (int t = 0; t < S_; ++t) {
        int cur = t & 1, nxt = cur ^ 1;
        const float* h0c = g_h0T[cur];
        float* h0n = g_h0T[nxt];
        const float* h1c = g_h1T[cur];
        float* h1n = g_h1T[nxt];

        // ---- P1: r0, z0 (K = 512, 2 chunks) ----
        float accr = g_Xp[0 * (size_t)S_ * H_ * B_ + ((size_t)t * H_ + n) * B_ + b];
        float accz = g_Xp[1 * (size_t)S_ * H_ * B_ + ((size_t)t * H_ + n) * B_ + b];
        {
            unsigned long long pr0 = 0, pr1 = 0, pz0 = 0, pz1 = 0;
            #pragma unroll
            for (int kc = 0; kc < H_; kc += KC) {
                stageT(sA, h0c + kc * B_);
                __syncthreads();
                mm2_chunk(sWr0 + cg * W0ROW + kc, sWz0 + cg * W0ROW + kc, aRow,
                          pr0, pr1, pz0, pz1);
                __syncthreads();
            }
            accr += unpack_sum(pr0) + unpack_sum(pr1);
            accz += unpack_sum(pz0) + unpack_sum(pz1);
        }
        float r0 = sigmoidf_(accr);
        float z0 = sigmoidf_(accz);
        g_r0T[n * B_ + b] = r0;
        grid_barrier();

        // ---- P2: h~0, h0 update ----
        float acch = g_Xp[2 * (size_t)S_ * H_ * B_ + ((size_t)t * H_ + n) * B_ + b];
        {
            unsigned long long p0 = 0, p1 = 0, p2 = 0, p3 = 0;
            #pragma unroll
            for (int kc = 0; kc < H_; kc += KC) {
                stageT_mul(sA, h0c + kc * B_, g_r0T + kc * B_);
                __syncthreads();
                mm1_chunk(sWh0 + cg * W0ROW + kc, aRow, p0, p1, p2, p3);
                __syncthreads();
            }
            acch += unpack_sum(p0) + unpack_sum(p1) + unpack_sum(p2) + unpack_sum(p3);
        }
        float ht0 = tanhf(acch);
        float h0old = h0c[n * B_ + b];
        float h0new = (1.f - z0) * h0old + z0 * ht0;
        h0n[n * B_ + b] = h0new;
        grid_barrier();

        // ---- P3: r1, z1 over comb = [h1, h0new], K = 1024 (4 chunks) ----
        accr = vbr1; accz = vbz1;
        {
            unsigned long long pr0 = 0, pr1 = 0, pz0 = 0, pz1 = 0;
            #pragma unroll
            for (int kc = 0; kc < 1024; kc += KC) {
                const float* src = (kc < H_) ? (h1c + kc * B_) : (h0n + (kc - H_) * B_);
                stageT(sA, src);
                __syncthreads();
                mm2_chunk(sWr1 + cg * W1ROW + kc, sWz1 + cg * W1ROW + kc, aRow,
                          pr0, pr1, pz0, pz1);
                __syncthreads();
            }
            accr += unpack_sum(pr0) + unpack_sum(pr1);
            accz += unpack_sum(pz0) + unpack_sum(pz1);
        }
        float r1 = sigmoidf_(accr);
        float z1 = sigmoidf_(accz);
        g_r1T[n * B_ + b] = r1;
        grid_barrier();

        // ---- P4: h~1, h1 update (no trailing grid barrier; see R2/R3 proof) ----
        acch = vbh1;
        {
            unsigned long long p0 = 0, p1 = 0, p2 = 0, p3 = 0;
            #pragma unroll
            for (int kc = 0; kc < 1024; kc += KC) {
                if (kc < H_) stageT_mul(sA, h1c + kc * B_, g_r1T + kc * B_);
                else         stageT(sA, h0n + (kc - H_) * B_);
                __syncthreads();
                mm1_chunk(sWh1 + cg * W1ROW + kc, aRow, p0, p1, p2, p3);
                __syncthreads();
            }
            acch += unpack_sum(p0) + unpack_sum(p1) + unpack_sum(p2) + unpack_sum(p3);
        }
        float ht1 = tanhf(acch);
        float h1old = h1c[n * B_ + b];
        float h1new = (1.f - z1) * h1old + z1 * ht1;
        h1n[n * B_ + b] = h1new;
        g_H1[((size_t)t * B_ + b) * H_ + n] = h1new;
    }
}

// ---------------- output GEMM: logits = H1 @ Wy^T + by (f32x2 inner) ----------------
__global__ void out_gemm(const float* __restrict__ Wy, const float* __restrict__ by,
                         float* __restrict__ out) {
    __shared__ float As[16][128];
    __shared__ float Bs[16][128];
    int n0 = blockIdx.x * 128;
    int m0 = blockIdx.y * 128;
    int tid = threadIdx.x;
    int tx = tid % 16, ty = tid / 16;
    unsigned long long acc2[8][4];
    #pragma unroll
    for (int i = 0; i < 8; i++)
        #pragma unroll
        for (int j = 0; j < 4; j++) acc2[i][j] = 0ull;

    const float* A = g_H1;
    for (int k0 = 0; k0 < H_; k0 += 16) {
        #pragma unroll
        for (int r = 0; r < 2; r++) {
            int f = tid + r * 256;
            int row = f >> 2, q = f & 3;
            float4 v = *(const float4*)&A[(size_t)(m0 + row) * H_ + k0 + q * 4];
            As[q * 4 + 0][row] = v.x; As[q * 4 + 1][row] = v.y;
            As[q * 4 + 2][row] = v.z; As[q * 4 + 3][row] = v.w;
        }
        #pragma unroll
        for (int r = 0; r < 2; r++) {
            int f = tid + r * 256;
            int row = f >> 2, q = f & 3;
            int nn = n0 + row;
            float4 v = make_float4(0.f, 0.f, 0.f, 0.f);
            if (nn < V_) v = *(const float4*)&Wy[(size_t)nn * H_ + k0 + q * 4];
            Bs[q * 4 + 0][row] = v.x; Bs[q * 4 + 1][row] = v.y;
            Bs[q * 4 + 2][row] = v.z; Bs[q * 4 + 3][row] = v.w;
        }
        __syncthreads();
        #pragma unroll
        for (int kk = 0; kk < 16; kk++) {
            float a[8];
            *(float4*)&a[0] = *(const float4*)&As[kk][ty * 8];
            *(float4*)&a[4] = *(const float4*)&As[kk][ty * 8 + 4];
            ulonglong2 bv0 = *(const ulonglong2*)&Bs[kk][tx * 8];
            ulonglong2 bv1 = *(const ulonglong2*)&Bs[kk][tx * 8 + 4];
            unsigned long long ad[8];
            #pragma unroll
            for (int i = 0; i < 8; i++) ad[i] = dup2(a[i]);
            #pragma unroll
            for (int i = 0; i < 8; i++) {
                fma2(acc2[i][0], ad[i], bv0.x);
                fma2(acc2[i][1], ad[i], bv0.y);
                fma2(acc2[i][2], ad[i], bv1.x);
                fma2(acc2[i][3], ad[i], bv1.y);
            }
        }
        __syncthreads();
    }
    #pragma unroll
    for (int i = 0; i < 8; i++) {
        size_t row = (size_t)m0 + ty * 8 + i;
        #pragma unroll
        for (int jp = 0; jp < 4; jp++) {
            int v0 = n0 + tx * 8 + jp * 2;
            float lo = __uint_as_float((unsigned)acc2[i][jp]);
            float hi = __uint_as_float((unsigned)(acc2[i][jp] >> 32));
            if (v0 < V_)     out[row * V_ + v0]     = lo + by[v0];
            if (v0 + 1 < V_) out[row * V_ + v0 + 1] = hi + by[v0 + 1];
        }
    }
}

// ---------------- launch ----------------
extern "C" void kernel_launch(void* const* d_in, const int* in_sizes, int n_in,
                              void* d_out, int out_size) {
    const int*   inputs = (const int*)d_in[0];
    const float* hidden = (const float*)d_in[1];
    const float* emb    = (const float*)d_in[2];
    const float* W_r0 = (const float*)d_in[3];
    const float* b_r0 = (const float*)d_in[4];
    const float* W_z0 = (const float*)d_in[5];
    const float* b_z0 = (const float*)d_in[6];
    const float* W_h0 = (const float*)d_in[7];
    const float* b_h0 = (const float*)d_in[8];
    const float* W_r1 = (const float*)d_in[9];
    const float* b_r1 = (const float*)d_in[10];
    const float* W_z1 = (const float*)d_in[11];
    const float* b_z1 = (const float*)d_in[12];
    const float* W_h1 = (const float*)d_in[13];
    const float* b_h1 = (const float*)d_in[14];
    const float* Wy   = (const float*)d_in[15];
    const float* by   = (const float*)d_in[16];
    float* out = (float*)d_out;

    cudaFuncSetAttribute(recurrence_kernel, cudaFuncAttributeMaxDynamicSharedMemorySize,
                         SMEM_BYTES);

    xproj_gemm<<<dim3(3 * H_ / 128, (S_ * B_) / 128), 256>>>(inputs, emb, W_r0, W_z0, W_h0,
                                                             b_r0, b_z0, b_h0);
    init_hidden_kernel<<<(B_ * H_ + 255) / 256, 256>>>(hidden);
    recurrence_kernel<<<NB, TPB, SMEM_BYTES>>>(W_r0, W_z0, W_h0, W_r1, W_z1, W_h1,
                                               b_r1, b_z1, b_h1);
    out_gemm<<<dim3((V_ + 127) / 128, (S_ * B_) / 128), 256>>>(Wy, by, out);

    long long logits_elems = (long long)S_ * B_ * V_;
    if ((long long)out_size >= logits_elems + 2LL * B_ * H_) {
        write_hidden_kernel<<<(B_ * H_ + 255) / 256, 256>>>(out, logits_elems);
    }
}

// round 5
// speedup vs baseline: 1.0841x; 1.0538x over previous
#include <cuda_runtime.h>
#include <math.h>

// Problem constants
#define S_ 128
#define B_ 64
#define V_ 10000
#define E_ 256
#define H_ 512

// Recurrence config: 64 CTAs x 8 columns, 256 threads, KC=128 double-buffered
#define NB 64
#define TPB 256
#define KC 128

// ---------------- device scratch (static, allocation-free) ----------------
__device__ float g_h0T[2][H_ * B_];      // h0 transposed [k][b], ping-pong
__device__ float g_h1T[2][H_ * B_];
__device__ float g_rh0[H_ * B_];         // r0 * h0_old, [k][b]
__device__ float g_rh1[H_ * B_];         // r1 * h1_old, [k][b]
__device__ float g_Xp[3u * S_ * H_ * B_];    // x-projections [g][t][n][b]
__device__ float g_H1[(size_t)S_ * B_ * H_]; // h1 all steps [t*B+b][k]
__device__ unsigned g_bar_count = 0;
__device__ unsigned g_genv[16 * 32];     // release flags, 128B apart

// ---------------- packed f32x2 helpers ----------------
__device__ __forceinline__ void fma2(unsigned long long& acc, unsigned long long a,
                                     unsigned long long w) {
    asm("fma.rn.f32x2 %0, %1, %2, %0;" : "+l"(acc) : "l"(a), "l"(w));
}
__device__ __forceinline__ float unpack_sum(unsigned long long v) {
    return __uint_as_float((unsigned)v) + __uint_as_float((unsigned)(v >> 32));
}
__device__ __forceinline__ unsigned long long dup2(float f) {
    unsigned long long d;
    asm("mov.b64 %0, {%1, %1};" : "=l"(d) : "r"(__float_as_uint(f)));
    return d;
}

__device__ __forceinline__ float sigmoidf_(float x) { return 1.0f / (1.0f + expf(-x)); }

// ---------------- grid barrier (64 CTAs, distributed release flags) ----------------
__device__ __forceinline__ void grid_barrier() {
    __syncthreads();
    if (threadIdx.x == 0) {
        __threadfence();
        unsigned slot = (blockIdx.x & 15) * 32;
        unsigned old = *((volatile unsigned*)&g_genv[slot]);
        unsigned t = atomicAdd(&g_bar_count, 1u);
        if (t == NB - 1) {
            g_bar_count = 0;
            __threadfence();
            #pragma unroll
            for (int i = 0; i < 16; i++)
                *((volatile unsigned*)&g_genv[i * 32]) = old + 1;
        } else {
            while (*((volatile unsigned*)&g_genv[slot]) == old) { }
        }
        __threadfence();
    }
    __syncthreads();
}

// ---------------- recurrence smem layout (floats) ----------------
// W0: 3 gates x 8 rows x 516 ; W1: 3 gates x 8 rows x 1028 ; sA: 2 x 64 x 132
#define W0ROW 516
#define W1ROW 1028
#define W0GATE (8 * W0ROW)           // 4128
#define W1GATE (8 * W1ROW)           // 8224
#define SM_W1 (3 * W0GATE)           // 12384
#define SM_SA (SM_W1 + 3 * W1GATE)   // 37056
#define SAROW 132
#define SABUF (B_ * SAROW)           // 8448
#define SM_FLOATS (SM_SA + 2 * SABUF)
#define SMEM_BYTES (SM_FLOATS * 4)   // 215808

// ---------------- staging: global [k][b] -> regs -> smem [b][k] ----------------
__device__ __forceinline__ void gather32(float* rg, const float* __restrict__ src) {
    int b = threadIdx.x & 63;
    int kq = threadIdx.x >> 6;               // 0..3, 32 k each
    const float* s = src + kq * 32 * B_ + b;
    #pragma unroll
    for (int i = 0; i < 32; i++) rg[i] = s[i * B_];
}
__device__ __forceinline__ void sts32(float* buf, const float* rg) {
    int b = threadIdx.x & 63;
    int kq = threadIdx.x >> 6;
    float* d = buf + b * SAROW + kq * 32;
    #pragma unroll
    for (int i = 0; i < 32; i += 4)
        *(float4*)(d + i) = make_float4(rg[i], rg[i + 1], rg[i + 2], rg[i + 3]);
}

// ---------------- chunk matmuls (2 b-rows per thread, f32x2) ----------------
__device__ __forceinline__ void mm2b(const float* a0, const float* a1,
                                     const float* wr, const float* wz,
                                     unsigned long long* pr, unsigned long long* pz) {
    #pragma unroll
    for (int kk = 0; kk < KC; kk += 4) {
        ulonglong2 w1 = *(const ulonglong2*)(wr + kk);
        ulonglong2 w2 = *(const ulonglong2*)(wz + kk);
        ulonglong2 x0 = *(const ulonglong2*)(a0 + kk);
        ulonglong2 x1 = *(const ulonglong2*)(a1 + kk);
        fma2(pr[0], x0.x, w1.x); fma2(pr[1], x0.y, w1.y);
        fma2(pr[2], x1.x, w1.x); fma2(pr[3], x1.y, w1.y);
        fma2(pz[0], x0.x, w2.x); fma2(pz[1], x0.y, w2.y);
        fma2(pz[2], x1.x, w2.x); fma2(pz[3], x1.y, w2.y);
    }
}
__device__ __forceinline__ void mm1b(const float* a0, const float* a1,
                                     const float* wh, unsigned long long* ph) {
    #pragma unroll
    for (int kk = 0; kk < KC; kk += 4) {
        ulonglong2 w = *(const ulonglong2*)(wh + kk);
        ulonglong2 x0 = *(const ulonglong2*)(a0 + kk);
        ulonglong2 x1 = *(const ulonglong2*)(a1 + kk);
        fma2(ph[0], x0.x, w.x); fma2(ph[1], x0.y, w.y);
        fma2(ph[2], x1.x, w.x); fma2(ph[3], x1.y, w.y);
    }
}
__device__ __forceinline__ void mm3b(const float* a0, const float* a1,
                                     const float* wr, const float* wz, const float* wh,
                                     unsigned long long* pr, unsigned long long* pz,
                                     unsigned long long* ph) {
    #pragma unroll
    for (int kk = 0; kk < KC; kk += 4) {
        ulonglong2 w1 = *(const ulonglong2*)(wr + kk);
        ulonglong2 w2 = *(const ulonglong2*)(wz + kk);
        ulonglong2 w3 = *(const ulonglong2*)(wh + kk);
        ulonglong2 x0 = *(const ulonglong2*)(a0 + kk);
        ulonglong2 x1 = *(const ulonglong2*)(a1 + kk);
        fma2(pr[0], x0.x, w1.x); fma2(pr[1], x0.y, w1.y);
        fma2(pr[2], x1.x, w1.x); fma2(pr[3], x1.y, w1.y);
        fma2(pz[0], x0.x, w2.x); fma2(pz[1], x0.y, w2.y);
        fma2(pz[2], x1.x, w2.x); fma2(pz[3], x1.y, w2.y);
        fma2(ph[0], x0.x, w3.x); fma2(ph[1], x0.y, w3.y);
        fma2(ph[2], x1.x, w3.x); fma2(ph[3], x1.y, w3.y);
    }
}

// ---------------- init / finalize ----------------
__global__ void init_hidden_kernel(const float* __restrict__ hidden) {
    int i = blockIdx.x * blockDim.x + threadIdx.x;
    if (i < B_ * H_) {
        int b = i / H_, k = i % H_;
        g_h0T[0][k * B_ + b] = hidden[0 * B_ * H_ + i];
        g_h1T[0][k * B_ + b] = hidden[1 * B_ * H_ + i];
    }
}
__global__ void write_hidden_kernel(float* __restrict__ out, long long off) {
    int i = blockIdx.x * blockDim.x + threadIdx.x;
    if (i < B_ * H_) {
        int b = i / H_, k = i % H_;
        out[off + i] = g_h0T[0][k * B_ + b];              // S even -> final parity 0
        out[off + B_ * H_ + i] = g_h1T[0][k * B_ + b];
    }
}

// ---------------- xproj GEMM: Xp_g = emb(tok) @ Wg0[:,H:]^T + bg0 ----------------
__global__ void xproj_gemm(const int* __restrict__ tok, const float* __restrict__ emb,
                           const float* __restrict__ Wr0, const float* __restrict__ Wz0,
                           const float* __restrict__ Wh0,
                           const float* __restrict__ br0, const float* __restrict__ bz0,
                           const float* __restrict__ bh0) {
    __shared__ float As[16][128];
    __shared__ float Bs[16][128];
    __shared__ int stok[128];
    int n0 = blockIdx.x * 128;
    int m0 = blockIdx.y * 128;
    int g = n0 / H_;
    int nb = n0 % H_;
    const float* W = (g == 0) ? Wr0 : (g == 1) ? Wz0 : Wh0;
    const float* bias = (g == 0) ? br0 : (g == 1) ? bz0 : bh0;
    int tid = threadIdx.x;
    if (tid < 128) stok[tid] = tok[m0 + tid];
    __syncthreads();
    int tx = tid % 16, ty = tid / 16;
    float acc[8][8];
    #pragma unroll
    for (int i = 0; i < 8; i++)
        #pragma unroll
        for (int j = 0; j < 8; j++) acc[i][j] = 0.f;

    for (int k0 = 0; k0 < E_; k0 += 16) {
        #pragma unroll
        for (int r = 0; r < 2; r++) {
            int f = tid + r * 256;
            int row = f >> 2, q = f & 3;
            int t = stok[row];
            float4 v = *(const float4*)&emb[(size_t)t * E_ + k0 + q * 4];
            As[q * 4 + 0][row] = v.x; As[q * 4 + 1][row] = v.y;
            As[q * 4 + 2][row] = v.z; As[q * 4 + 3][row] = v.w;
        }
        #pragma unroll
        for (int r = 0; r < 2; r++) {
            int f = tid + r * 256;
            int row = f >> 2, q = f & 3;
            float4 v = *(const float4*)&W[(size_t)(nb + row) * (H_ + E_) + H_ + k0 + q * 4];
            Bs[q * 4 + 0][row] = v.x; Bs[q * 4 + 1][row] = v.y;
            Bs[q * 4 + 2][row] = v.z; Bs[q * 4 + 3][row] = v.w;
        }
        __syncthreads();
        #pragma unroll
        for (int kk = 0; kk < 16; kk++) {
            float a[8], bv[8];
            *(float4*)&a[0] = *(const float4*)&As[kk][ty * 8];
            *(float4*)&a[4] = *(const float4*)&As[kk][ty * 8 + 4];
            *(float4*)&bv[0] = *(const float4*)&Bs[kk][tx * 8];
            *(float4*)&bv[4] = *(const float4*)&Bs[kk][tx * 8 + 4];
            #pragma unroll
            for (int i = 0; i < 8; i++)
                #pragma unroll
                for (int j = 0; j < 8; j++) acc[i][j] = fmaf(a[i], bv[j], acc[i][j]);
        }
        __syncthreads();
    }
    float bfrag[8];
    *(float4*)&bfrag[0] = *(const float4*)&bias[nb + tx * 8];
    *(float4*)&bfrag[4] = *(const float4*)&bias[nb + tx * 8 + 4];
    float* Xg = g_Xp + (size_t)g * S_ * H_ * B_;
    #pragma unroll
    for (int i = 0; i < 8; i++) {
        int row = m0 + ty * 8 + i;
        int t = row >> 6, b = row & 63;
        #pragma unroll
        for (int j = 0; j < 8; j++) {
            int n = nb + tx * 8 + j;
            Xg[((size_t)t * H_ + n) * B_ + b] = acc[i][j] + bfrag[j];
        }
    }
}

// ---------------- persistent recurrence kernel (64 CTAs x 8 cols) ----------------
// thread: cg = tid&7 -> column n = n0+cg ; bp = tid>>3 -> b0 = 2*bp, b1 = b0+1.
__global__ void __launch_bounds__(TPB)
recurrence_kernel(const float* __restrict__ Wr0, const float* __restrict__ Wz0,
                  const float* __restrict__ Wh0,
                  const float* __restrict__ Wr1, const float* __restrict__ Wz1,
                  const float* __restrict__ Wh1,
                  const float* __restrict__ br1, const float* __restrict__ bz1,
                  const float* __restrict__ bh1) {
    extern __shared__ float sm[];
    int tid = threadIdx.x;
    int n0 = blockIdx.x * 8;
    int cg = tid & 7;
    int bp = tid >> 3;
    int b0 = bp * 2, b1 = b0 + 1;
    int n = n0 + cg;

    // -------- preload weights (once) --------
    for (int j = tid; j < 3072; j += TPB) {               // layer0 h-part: 3x8x128 float4
        int g = j >> 10, rem = j & 1023;
        int r = rem >> 7, k4 = rem & 127;
        const float* Ws = (g == 0) ? Wr0 : (g == 1) ? Wz0 : Wh0;
        *(float4*)(sm + g * W0GATE + r * W0ROW + k4 * 4) =
            *(const float4*)&Ws[(size_t)(n0 + r) * (H_ + E_) + k4 * 4];
    }
    for (int j = tid; j < 6144; j += TPB) {               // layer1: 3x8x256 float4
        int g = j >> 11, rem = j & 2047;
        int r = rem >> 8, k4 = rem & 255;
        const float* Ws = (g == 0) ? Wr1 : (g == 1) ? Wz1 : Wh1;
        *(float4*)(sm + SM_W1 + g * W1GATE + r * W1ROW + k4 * 4) =
            *(const float4*)&Ws[(size_t)(n0 + r) * 1024 + k4 * 4];
    }
    const float* wr0p = sm + 0 * W0GATE + cg * W0ROW;
    const float* wz0p = sm + 1 * W0GATE + cg * W0ROW;
    const float* wh0p = sm + 2 * W0GATE + cg * W0ROW;
    const float* wr1p = sm + SM_W1 + 0 * W1GATE + cg * W1ROW;
    const float* wz1p = sm + SM_W1 + 1 * W1GATE + cg * W1ROW;
    const float* wh1p = sm + SM_W1 + 2 * W1GATE + cg * W1ROW;
    float vbr1 = br1[n], vbz1 = bz1[n], vbh1 = bh1[n];
    float* sA = sm + SM_SA;
    grid_barrier();   // weights + init_hidden visible

    float rg[32];

    for (int t = 0; t < S_; ++t) {
        int cur = t & 1, nxt = cur ^ 1;
        const float* h0c = g_h0T[cur];
        float* h0n = g_h0T[nxt];
        const float* h1c = g_h1T[cur];
        float* h1n = g_h1T[nxt];

        float z0a, z0b, h0oa, h0ob;
        // ======== P1: r0, z0 over h0c (K=512, 4 chunks) ========
        {
            unsigned long long pr[4] = {0, 0, 0, 0}, pz[4] = {0, 0, 0, 0};
            gather32(rg, h0c);
            sts32(sA, rg);
            __syncthreads();
            #pragma unroll
            for (int c = 0; c < 4; c++) {
                if (c < 3) gather32(rg, h0c + (c + 1) * KC * B_);
                float* buf = sA + (c & 1) * SABUF;
                mm2b(buf + b0 * SAROW, buf + b1 * SAROW,
                     wr0p + c * KC, wz0p + c * KC, pr, pz);
                if (c < 3) sts32(sA + ((c + 1) & 1) * SABUF, rg);
                __syncthreads();
            }
            size_t xo = ((size_t)t * H_ + n) * B_;
            float ra = sigmoidf_(unpack_sum(pr[0]) + unpack_sum(pr[1]) + g_Xp[xo + b0]);
            float rb = sigmoidf_(unpack_sum(pr[2]) + unpack_sum(pr[3]) + g_Xp[xo + b1]);
            size_t x1o = (size_t)S_ * H_ * B_;
            z0a = sigmoidf_(unpack_sum(pz[0]) + unpack_sum(pz[1]) + g_Xp[x1o + xo + b0]);
            z0b = sigmoidf_(unpack_sum(pz[2]) + unpack_sum(pz[3]) + g_Xp[x1o + xo + b1]);
            h0oa = h0c[n * B_ + b0];
            h0ob = h0c[n * B_ + b1];
            g_rh0[n * B_ + b0] = ra * h0oa;
            g_rh0[n * B_ + b1] = rb * h0ob;
        }
        grid_barrier();

        // ======== P2: h~0 over rh0 (K=512), h0 update ========
        {
            unsigned long long ph[4] = {0, 0, 0, 0};
            gather32(rg, g_rh0);
            sts32(sA, rg);
            __syncthreads();
            #pragma unroll
            for (int c = 0; c < 4; c++) {
                if (c < 3) gather32(rg, g_rh0 + (c + 1) * KC * B_);
                float* buf = sA + (c & 1) * SABUF;
                mm1b(buf + b0 * SAROW, buf + b1 * SAROW, wh0p + c * KC, ph);
                if (c < 3) sts32(sA + ((c + 1) & 1) * SABUF, rg);
                __syncthreads();
            }
            size_t xo = 2 * (size_t)S_ * H_ * B_ + ((size_t)t * H_ + n) * B_;
            float hta = tanhf(unpack_sum(ph[0]) + unpack_sum(ph[1]) + g_Xp[xo + b0]);
            float htb = tanhf(unpack_sum(ph[2]) + unpack_sum(ph[3]) + g_Xp[xo + b1]);
            h0n[n * B_ + b0] = (1.f - z0a) * h0oa + z0a * hta;
            h0n[n * B_ + b1] = (1.f - z0b) * h0ob + z0b * htb;
        }
        grid_barrier();

        // ======== P3: r1, z1 over [h1c | h0n] (K=1024) + h~1 partial on h0n half ====
        float z1a, z1b, h1oa, h1ob;
        unsigned long long ph1[4] = {0, 0, 0, 0};     // persists into P4
        {
            unsigned long long pr[4] = {0, 0, 0, 0}, pz[4] = {0, 0, 0, 0};
            gather32(rg, h1c);
            sts32(sA, rg);
            __syncthreads();
            #pragma unroll
            for (int c = 0; c < 8; c++) {
                if (c < 7) {
                    const float* nsrc = (c + 1 < 4) ? (h1c + (c + 1) * KC * B_)
                                                    : (h0n + (c + 1 - 4) * KC * B_);
                    gather32(rg, nsrc);
                }
                float* buf = sA + (c & 1) * SABUF;
                const float* a0 = buf + b0 * SAROW;
                const float* a1 = buf + b1 * SAROW;
                if (c < 4) {
                    mm2b(a0, a1, wr1p + c * KC, wz1p + c * KC, pr, pz);
                } else {
                    int kofs = H_ + (c - 4) * KC;      // cols 512..1023
                    mm3b(a0, a1, wr1p + kofs, wz1p + kofs, wh1p + kofs, pr, pz, ph1);
                }
                if (c < 7) sts32(sA + ((c + 1) & 1) * SABUF, rg);
                __syncthreads();
            }
            float ra = sigmoidf_(unpack_sum(pr[0]) + unpack_sum(pr[1]) + vbr1);
            float rb = sigmoidf_(unpack_sum(pr[2]) + unpack_sum(pr[3]) + vbr1);
            z1a = sigmoidf_(unpack_sum(pz[0]) + unpack_sum(pz[1]) + vbz1);
            z1b = sigmoidf_(unpack_sum(pz[2]) + unpack_sum(pz[3]) + vbz1);
            h1oa = h1c[n * B_ + b0];
            h1ob = h1c[n * B_ + b1];
            g_rh1[n * B_ + b0] = ra * h1oa;
            g_rh1[n * B_ + b1] = rb * h1ob;
        }
        grid_barrier();

        // ======== P4: finish h~1 over rh1 (K=512, Wh1 cols 0..511), h1 update ======
        {
            gather32(rg, g_rh1);
            sts32(sA, rg);
            __syncthreads();
            #pragma unroll
            for (int c = 0; c < 4; c++) {
                if (c < 3) gather32(rg, g_rh1 + (c + 1) * KC * B_);
                float* buf = sA + (c & 1) * SABUF;
                mm1b(buf + b0 * SAROW, buf + b1 * SAROW, wh1p + c * KC, ph1);
                if (c < 3) sts32(sA + ((c + 1) & 1) * SABUF, rg);
                __syncthreads();
            }
            float hta = tanhf(unpack_sum(ph1[0]) + unpack_sum(ph1[1]) + vbh1);
            float htb = tanhf(unpack_sum(ph1[2]) + unpack_sum(ph1[3]) + vbh1);
            float h1na = (1.f - z1a) * h1oa + z1a * hta;
            float h1nb = (1.f - z1b) * h1ob + z1b * htb;
            h1n[n * B_ + b0] = h1na;
            h1n[n * B_ + b1] = h1nb;
            g_H1[((size_t)t * B_ + b0) * H_ + n] = h1na;
            g_H1[((size_t)t * B_ + b1) * H_ + n] = h1nb;
        }
        // no barrier: next-P1-end barrier orders all P4 writes before next-P2/P3 reads
    }
}

// ---------------- output GEMM: logits = H1 @ Wy^T + by ----------------
// 128x128 tile, warp = 4ty x 8tx, split fragments (conflict-free, 4 wf/kk)
__global__ void out_gemm(const float* __restrict__ Wy, const float* __restrict__ by,
                         float* __restrict__ out) {
    __shared__ float As[16][128];
    __shared__ float Bs[16][128];
    int n0 = blockIdx.x * 128;
    int m0 = blockIdx.y * 128;
    int tid = threadIdx.x;
    int w = tid >> 5, l = tid & 31;
    int tx = (w & 1) * 8 + (l & 7);      // 0..15
    int ty = (w >> 1) * 4 + (l >> 3);    // 0..15

    unsigned long long acc2[8][4];
    #pragma unroll
    for (int i = 0; i < 8; i++)
        #pragma unroll
        for (int j = 0; j < 4; j++) acc2[i][j] = 0ull;

    const float* A = g_H1;
    for (int k0 = 0; k0 < H_; k0 += 16) {
        #pragma unroll
        for (int r = 0; r < 2; r++) {
            int f = tid + r * 256;
            int row = f >> 2, q = f & 3;
            float4 v = *(const float4*)&A[(size_t)(m0 + row) * H_ + k0 + q * 4];
            As[q * 4 + 0][row] = v.x; As[q * 4 + 1][row] = v.y;
            As[q * 4 + 2][row] = v.z; As[q * 4 + 3][row] = v.w;
        }
        #pragma unroll
        for (int r = 0; r < 2; r++) {
            int f = tid + r * 256;
            int row = f >> 2, q = f & 3;
            int nn = n0 + row;
            float4 v = make_float4(0.f, 0.f, 0.f, 0.f);
            if (nn < V_) v = *(const float4*)&Wy[(size_t)nn * H_ + k0 + q * 4];
            Bs[q * 4 + 0][row] = v.x; Bs[q * 4 + 1][row] = v.y;
            Bs[q * 4 + 2][row] = v.z; Bs[q * 4 + 3][row] = v.w;
        }
        __syncthreads();
        #pragma unroll
        for (int kk = 0; kk < 16; kk++) {
            float a[8];
            *(float4*)&a[0] = *(const float4*)&As[kk][ty * 4];
            *(float4*)&a[4] = *(const float4*)&As[kk][64 + ty * 4];
            ulonglong2 bv0 = *(const ulonglong2*)&Bs[kk][tx * 4];
            ulonglong2 bv1 = *(const ulonglong2*)&Bs[kk][64 + tx * 4];
            #pragma unroll
            for (int i = 0; i < 8; i++) {
                unsigned long long ad = dup2(a[i]);
                fma2(acc2[i][0], ad, bv0.x);
                fma2(acc2[i][1], ad, bv0.y);
                fma2(acc2[i][2], ad, bv1.x);
                fma2(acc2[i][3], ad, bv1.y);
            }
        }
        __syncthreads();
    }
    #pragma unroll
    for (int i = 0; i < 8; i++) {
        int rloc = (i < 4) ? (ty * 4 + i) : (64 + ty * 4 + i - 4);
        size_t row = (size_t)m0 + rloc;
        #pragma unroll
        for (int jp = 0; jp < 4; jp++) {
            int v0 = n0 + ((jp < 2) ? (tx * 4 + jp * 2) : (64 + tx * 4 + (jp - 2) * 2));
            float lo = __uint_as_float((unsigned)acc2[i][jp]);
            float hi = __uint_as_float((unsigned)(acc2[i][jp] >> 32));
            if (v0 < V_)     out[row * V_ + v0]     = lo + by[v0];
            if (v0 + 1 < V_) out[row * V_ + v0 + 1] = hi + by[v0 + 1];
        }
    }
}

// ---------------- launch ----------------
extern "C" void kernel_launch(void* const* d_in, const int* in_sizes, int n_in,
                              void* d_out, int out_size) {
    const int*   inputs = (const int*)d_in[0];
    const float* hidden = (const float*)d_in[1];
    const float* emb    = (const float*)d_in[2];
    const float* W_r0 = (const float*)d_in[3];
    const float* b_r0 = (const float*)d_in[4];
    const float* W_z0 = (const float*)d_in[5];
    const float* b_z0 = (const float*)d_in[6];
    const float* W_h0 = (const float*)d_in[7];
    const float* b_h0 = (const float*)d_in[8];
    const float* W_r1 = (const float*)d_in[9];
    const float* b_r1 = (const float*)d_in[10];
    const float* W_z1 = (const float*)d_in[11];
    const float* b_z1 = (const float*)d_in[12];
    const float* W_h1 = (const float*)d_in[13];
    const float* b_h1 = (const float*)d_in[14];
    const float* Wy   = (const float*)d_in[15];
    const float* by   = (const float*)d_in[16];
    float* out = (float*)d_out;

    cudaFuncSetAttribute(recurrence_kernel, cudaFuncAttributeMaxDynamicSharedMemorySize,
                         SMEM_BYTES);

    xproj_gemm<<<dim3(3 * H_ / 128, (S_ * B_) / 128), 256>>>(inputs, emb, W_r0, W_z0, W_h0,
                                                             b_r0, b_z0, b_h0);
    init_hidden_kernel<<<(B_ * H_ + 255) / 256, 256>>>(hidden);
    recurrence_kernel<<<NB, TPB, SMEM_BYTES>>>(W_r0, W_z0, W_h0, W_r1, W_z1, W_h1,
                                               b_r1, b_z1, b_h1);
    out_gemm<<<dim3((V_ + 127) / 128, (S_ * B_) / 128), 256>>>(Wy, by, out);

    long long logits_elems = (long long)S_ * B_ * V_;
    if ((long long)out_size >= logits_elems + 2LL * B_ * H_) {
        write_hidden_kernel<<<(B_ * H_ + 255) / 256, 256>>>(out, logits_elems);
    }
}

// round 6
// speedup vs baseline: 1.4048x; 1.2959x over previous
#include <cuda_runtime.h>
#include <math.h>

// Problem constants
#define S_ 128
#define B_ 64
#define V_ 10000
#define E_ 256
#define H_ 512

// Fused kernel config
#define NB 64            // recurrence CTAs
#define NCTA 148         // total CTAs (1 per SM, all co-resident)
#define TPB 256
#define KC 128
#define NTN 79           // logits n-tiles (79*128 >= 10000)
#define NTM 64           // logits m-tiles (8192/128)

// ---------------- device scratch ----------------
__device__ float g_h0T[2][H_ * B_];
__device__ float g_h1T[2][H_ * B_];
__device__ float g_rh0[H_ * B_];
__device__ float g_rh1[H_ * B_];
__device__ float g_Xp[3u * S_ * H_ * B_];
__device__ float g_H1[(size_t)S_ * B_ * H_];
__device__ unsigned g_bar_count = 0;
__device__ unsigned g_genv[16 * 32];
__device__ int g_progress;       // highest completed timestep t (reset to -1)
__device__ int g_tile_ctr;       // logits tile queue (reset to 0)

// ---------------- packed f32x2 helpers ----------------
__device__ __forceinline__ void fma2(unsigned long long& acc, unsigned long long a,
                                     unsigned long long w) {
    asm("fma.rn.f32x2 %0, %1, %2, %0;" : "+l"(acc) : "l"(a), "l"(w));
}
__device__ __forceinline__ float unpack_sum(unsigned long long v) {
    return __uint_as_float((unsigned)v) + __uint_as_float((unsigned)(v >> 32));
}
__device__ __forceinline__ unsigned long long dup2(float f) {
    unsigned long long d;
    asm("mov.b64 %0, {%1, %1};" : "=l"(d) : "r"(__float_as_uint(f)));
    return d;
}
__device__ __forceinline__ float sigmoidf_(float x) { return 1.0f / (1.0f + expf(-x)); }

// ---------------- grid barrier (recurrence CTAs only) ----------------
__device__ __forceinline__ void grid_barrier() {
    __syncthreads();
    if (threadIdx.x == 0) {
        __threadfence();
        unsigned slot = (blockIdx.x & 15) * 32;
        unsigned old = *((volatile unsigned*)&g_genv[slot]);
        unsigned t = atomicAdd(&g_bar_count, 1u);
        if (t == NB - 1) {
            g_bar_count = 0;
            __threadfence();
            #pragma unroll
            for (int i = 0; i < 16; i++)
                *((volatile unsigned*)&g_genv[i * 32]) = old + 1;
        } else {
            while (*((volatile unsigned*)&g_genv[slot]) == old) { }
        }
        __threadfence();
    }
    __syncthreads();
}

// ---------------- recurrence smem layout ----------------
#define W0ROW 516
#define W1ROW 1028
#define W0GATE (8 * W0ROW)
#define W1GATE (8 * W1ROW)
#define SM_W1 (3 * W0GATE)
#define SM_SA (SM_W1 + 3 * W1GATE)
#define SAROW 132
#define SABUF (B_ * SAROW)
#define SM_FLOATS (SM_SA + 2 * SABUF)
#define SMEM_BYTES (SM_FLOATS * 4)   // 215808

// ---------------- staging ----------------
__device__ __forceinline__ void gather32(float* rg, const float* __restrict__ src) {
    int b = threadIdx.x & 63;
    int kq = threadIdx.x >> 6;
    const float* s = src + kq * 32 * B_ + b;
    #pragma unroll
    for (int i = 0; i < 32; i++) rg[i] = s[i * B_];
}
__device__ __forceinline__ void sts32(float* buf, const float* rg) {
    int b = threadIdx.x & 63;
    int kq = threadIdx.x >> 6;
    float* d = buf + b * SAROW + kq * 32;
    #pragma unroll
    for (int i = 0; i < 32; i += 4)
        *(float4*)(d + i) = make_float4(rg[i], rg[i + 1], rg[i + 2], rg[i + 3]);
}

// ---------------- chunk matmuls ----------------
__device__ __forceinline__ void mm2b(const float* a0, const float* a1,
                                     const float* wr, const float* wz,
                                     unsigned long long* pr, unsigned long long* pz) {
    #pragma unroll
    for (int kk = 0; kk < KC; kk += 4) {
        ulonglong2 w1 = *(const ulonglong2*)(wr + kk);
        ulonglong2 w2 = *(const ulonglong2*)(wz + kk);
        ulonglong2 x0 = *(const ulonglong2*)(a0 + kk);
        ulonglong2 x1 = *(const ulonglong2*)(a1 + kk);
        fma2(pr[0], x0.x, w1.x); fma2(pr[1], x0.y, w1.y);
        fma2(pr[2], x1.x, w1.x); fma2(pr[3], x1.y, w1.y);
        fma2(pz[0], x0.x, w2.x); fma2(pz[1], x0.y, w2.y);
        fma2(pz[2], x1.x, w2.x); fma2(pz[3], x1.y, w2.y);
    }
}
__device__ __forceinline__ void mm1b(const float* a0, const float* a1,
                                     const float* wh, unsigned long long* ph) {
    #pragma unroll
    for (int kk = 0; kk < KC; kk += 4) {
        ulonglong2 w = *(const ulonglong2*)(wh + kk);
        ulonglong2 x0 = *(const ulonglong2*)(a0 + kk);
        ulonglong2 x1 = *(const ulonglong2*)(a1 + kk);
        fma2(ph[0], x0.x, w.x); fma2(ph[1], x0.y, w.y);
        fma2(ph[2], x1.x, w.x); fma2(ph[3], x1.y, w.y);
    }
}

// ---------------- init / finalize ----------------
__global__ void init_hidden_kernel(const float* __restrict__ hidden) {
    int i = blockIdx.x * blockDim.x + threadIdx.x;
    if (i < B_ * H_) {
        int b = i / H_, k = i % H_;
        g_h0T[0][k * B_ + b] = hidden[0 * B_ * H_ + i];
        g_h1T[0][k * B_ + b] = hidden[1 * B_ * H_ + i];
    }
    if (blockIdx.x == 0 && threadIdx.x == 0) {
        g_progress = -1;
        g_tile_ctr = 0;
    }
}
__global__ void write_hidden_kernel(float* __restrict__ out, long long off) {
    int i = blockIdx.x * blockDim.x + threadIdx.x;
    if (i < B_ * H_) {
        int b = i / H_, k = i % H_;
        out[off + i] = g_h0T[0][k * B_ + b];              // h0(127) lands in buf 0
        out[off + B_ * H_ + i] = g_h1T[0][k * B_ + b];    // h1(127) lands in buf 0
    }
}

// ---------------- xproj GEMM ----------------
__global__ void xproj_gemm(const int* __restrict__ tok, const float* __restrict__ emb,
                           const float* __restrict__ Wr0, const float* __restrict__ Wz0,
                           const float* __restrict__ Wh0,
                           const float* __restrict__ br0, const float* __restrict__ bz0,
                           const float* __restrict__ bh0) {
    __shared__ float As[16][128];
    __shared__ float Bs[16][128];
    __shared__ int stok[128];
    int n0 = blockIdx.x * 128;
    int m0 = blockIdx.y * 128;
    int g = n0 / H_;
    int nb = n0 % H_;
    const float* W = (g == 0) ? Wr0 : (g == 1) ? Wz0 : Wh0;
    const float* bias = (g == 0) ? br0 : (g == 1) ? bz0 : bh0;
    int tid = threadIdx.x;
    if (tid < 128) stok[tid] = tok[m0 + tid];
    __syncthreads();
    int tx = tid % 16, ty = tid / 16;
    float acc[8][8];
    #pragma unroll
    for (int i = 0; i < 8; i++)
        #pragma unroll
        for (int j = 0; j < 8; j++) acc[i][j] = 0.f;

    for (int k0 = 0; k0 < E_; k0 += 16) {
        #pragma unroll
        for (int r = 0; r < 2; r++) {
            int f = tid + r * 256;
            int row = f >> 2, q = f & 3;
            int t = stok[row];
            float4 v = *(const float4*)&emb[(size_t)t * E_ + k0 + q * 4];
            As[q * 4 + 0][row] = v.x; As[q * 4 + 1][row] = v.y;
            As[q * 4 + 2][row] = v.z; As[q * 4 + 3][row] = v.w;
        }
        #pragma unroll
        for (int r = 0; r < 2; r++) {
            int f = tid + r * 256;
            int row = f >> 2, q = f & 3;
            float4 v = *(const float4*)&W[(size_t)(nb + row) * (H_ + E_) + H_ + k0 + q * 4];
            Bs[q * 4 + 0][row] = v.x; Bs[q * 4 + 1][row] = v.y;
            Bs[q * 4 + 2][row] = v.z; Bs[q * 4 + 3][row] = v.w;
        }
        __syncthreads();
        #pragma unroll
        for (int kk = 0; kk < 16; kk++) {
            float a[8], bv[8];
            *(float4*)&a[0] = *(const float4*)&As[kk][ty * 8];
            *(float4*)&a[4] = *(const float4*)&As[kk][ty * 8 + 4];
            *(float4*)&bv[0] = *(const float4*)&Bs[kk][tx * 8];
            *(float4*)&bv[4] = *(const float4*)&Bs[kk][tx * 8 + 4];
            #pragma unroll
            for (int i = 0; i < 8; i++)
                #pragma unroll
                for (int j = 0; j < 8; j++) acc[i][j] = fmaf(a[i], bv[j], acc[i][j]);
        }
        __syncthreads();
    }
    float bfrag[8];
    *(float4*)&bfrag[0] = *(const float4*)&bias[nb + tx * 8];
    *(float4*)&bfrag[4] = *(const float4*)&bias[nb + tx * 8 + 4];
    float* Xg = g_Xp + (size_t)g * S_ * H_ * B_;
    #pragma unroll
    for (int i = 0; i < 8; i++) {
        int row = m0 + ty * 8 + i;
        int t = row >> 6, b = row & 63;
        #pragma unroll
        for (int j = 0; j < 8; j++) {
            int n = nb + tx * 8 + j;
            Xg[((size_t)t * H_ + n) * B_ + b] = acc[i][j] + bfrag[j];
        }
    }
}

// ---------------- recurrence role (CTAs 0..63), layer-pipelined ----------------
__device__ void recurrence_role(float* sm,
                  const float* __restrict__ Wr0, const float* __restrict__ Wz0,
                  const float* __restrict__ Wh0,
                  const float* __restrict__ Wr1, const float* __restrict__ Wz1,
                  const float* __restrict__ Wh1,
                  const float* __restrict__ br1, const float* __restrict__ bz1,
                  const float* __restrict__ bh1) {
    int tid = threadIdx.x;
    int n0 = blockIdx.x * 8;
    int cg = tid & 7;
    int bp = tid >> 3;
    int b0 = bp * 2, b1 = b0 + 1;
    int n = n0 + cg;

    for (int j = tid; j < 3072; j += TPB) {
        int g = j >> 10, rem = j & 1023;
        int r = rem >> 7, k4 = rem & 127;
        const float* Ws = (g == 0) ? Wr0 : (g == 1) ? Wz0 : Wh0;
        *(float4*)(sm + g * W0GATE + r * W0ROW + k4 * 4) =
            *(const float4*)&Ws[(size_t)(n0 + r) * (H_ + E_) + k4 * 4];
    }
    for (int j = tid; j < 6144; j += TPB) {
        int g = j >> 11, rem = j & 2047;
        int r = rem >> 8, k4 = rem & 255;
        const float* Ws = (g == 0) ? Wr1 : (g == 1) ? Wz1 : Wh1;
        *(float4*)(sm + SM_W1 + g * W1GATE + r * W1ROW + k4 * 4) =
            *(const float4*)&Ws[(size_t)(n0 + r) * 1024 + k4 * 4];
    }
    const float* wr0p = sm + 0 * W0GATE + cg * W0ROW;
    const float* wz0p = sm + 1 * W0GATE + cg * W0ROW;
    const float* wh0p = sm + 2 * W0GATE + cg * W0ROW;
    const float* wr1p = sm + SM_W1 + 0 * W1GATE + cg * W1ROW;
    const float* wz1p = sm + SM_W1 + 1 * W1GATE + cg * W1ROW;
    const float* wh1p = sm + SM_W1 + 2 * W1GATE + cg * W1ROW;
    float vbr1 = br1[n], vbz1 = bz1[n], vbh1 = bh1[n];
    float* sA = sm + SM_SA;
    __syncthreads();     // weights visible CTA-locally (init kernel preceded)

    float rg[32];
    float z0a = 0.f, z0b = 0.f, h0oa = 0.f, h0ob = 0.f;
    float z1a = 0.f, z1b = 0.f, h1oa = 0.f, h1ob = 0.f;

    // Tick u: PhA = r0z0(t=u) + r1z1(t=u-1); PhB = h~0(t=u) + h~1(t=u-1)
    for (int u = 0; u <= S_; ++u) {
        const float* h0c = g_h0T[u & 1];          // h0(u-1)
        float* h0n = (float*)g_h0T[(u & 1) ^ 1];  // h0(u) dest
        const float* h1c = g_h1T[(u + 1) & 1];    // h1(u-2)
        float* h1n = (float*)g_h1T[u & 1];        // h1(u-1) dest

        // ======== PhA ========
        if (u < S_) {       // layer0 gates: r0,z0 over h0c (K=512)
            unsigned long long pr[4] = {0,0,0,0}, pz[4] = {0,0,0,0};
            gather32(rg, h0c);
            sts32(sA, rg);
            __syncthreads();
            #pragma unroll
            for (int c = 0; c < 4; c++) {
                if (c < 3) gather32(rg, h0c + (c + 1) * KC * B_);
                float* buf = sA + (c & 1) * SABUF;
                mm2b(buf + b0 * SAROW, buf + b1 * SAROW,
                     wr0p + c * KC, wz0p + c * KC, pr, pz);
                if (c < 3) sts32(sA + ((c + 1) & 1) * SABUF, rg);
                __syncthreads();
            }
            size_t xo = ((size_t)u * H_ + n) * B_;
            float ra = sigmoidf_(unpack_sum(pr[0]) + unpack_sum(pr[1]) + g_Xp[xo + b0]);
            float rb = sigmoidf_(unpack_sum(pr[2]) + unpack_sum(pr[3]) + g_Xp[xo + b1]);
            size_t x1o = (size_t)S_ * H_ * B_;
            z0a = sigmoidf_(unpack_sum(pz[0]) + unpack_sum(pz[1]) + g_Xp[x1o + xo + b0]);
            z0b = sigmoidf_(unpack_sum(pz[2]) + unpack_sum(pz[3]) + g_Xp[x1o + xo + b1]);
            h0oa = h0c[n * B_ + b0];
            h0ob = h0c[n * B_ + b1];
            g_rh0[n * B_ + b0] = ra * h0oa;
            g_rh0[n * B_ + b1] = rb * h0ob;
        }
        if (u > 0) {        // layer1 gates: r1,z1 over [h1(u-2) | h0(u-1)] (K=1024)
            unsigned long long pr[4] = {0,0,0,0}, pz[4] = {0,0,0,0};
            gather32(rg, h1c);
            sts32(sA, rg);
            __syncthreads();
            #pragma unroll
            for (int c = 0; c < 8; c++) {
                if (c < 7) {
                    const float* nsrc = (c + 1 < 4) ? (h1c + (c + 1) * KC * B_)
                                                    : (h0c + (c + 1 - 4) * KC * B_);
                    gather32(rg, nsrc);
                }
                float* buf = sA + (c & 1) * SABUF;
                mm2b(buf + b0 * SAROW, buf + b1 * SAROW,
                     wr1p + c * KC, wz1p + c * KC, pr, pz);
                if (c < 7) sts32(sA + ((c + 1) & 1) * SABUF, rg);
                __syncthreads();
            }
            float ra = sigmoidf_(unpack_sum(pr[0]) + unpack_sum(pr[1]) + vbr1);
            float rb = sigmoidf_(unpack_sum(pr[2]) + unpack_sum(pr[3]) + vbr1);
            z1a = sigmoidf_(unpack_sum(pz[0]) + unpack_sum(pz[1]) + vbz1);
            z1b = sigmoidf_(unpack_sum(pz[2]) + unpack_sum(pz[3]) + vbz1);
            h1oa = h1c[n * B_ + b0];
            h1ob = h1c[n * B_ + b1];
            g_rh1[n * B_ + b0] = ra * h1oa;
            g_rh1[n * B_ + b1] = rb * h1ob;
        }
        grid_barrier();

        // ======== PhB ========
        if (u < S_) {       // h~0 over rh0 (K=512), h0 update
            unsigned long long ph[4] = {0,0,0,0};
            gather32(rg, g_rh0);
            sts32(sA, rg);
            __syncthreads();
            #pragma unroll
            for (int c = 0; c < 4; c++) {
                if (c < 3) gather32(rg, g_rh0 + (c + 1) * KC * B_);
                float* buf = sA + (c & 1) * SABUF;
                mm1b(buf + b0 * SAROW, buf + b1 * SAROW, wh0p + c * KC, ph);
                if (c < 3) sts32(sA + ((c + 1) & 1) * SABUF, rg);
                __syncthreads();
            }
            size_t xo = 2 * (size_t)S_ * H_ * B_ + ((size_t)u * H_ + n) * B_;
            float hta = tanhf(unpack_sum(ph[0]) + unpack_sum(ph[1]) + g_Xp[xo + b0]);
            float htb = tanhf(unpack_sum(ph[2]) + unpack_sum(ph[3]) + g_Xp[xo + b1]);
            h0n[n * B_ + b0] = (1.f - z0a) * h0oa + z0a * hta;
            h0n[n * B_ + b1] = (1.f - z0b) * h0ob + z0b * htb;
        }
        if (u > 0) {        // h~1 over [rh1 | h0(u-1)] (K=1024), h1 update
            unsigned long long ph[4] = {0,0,0,0};
            gather32(rg, g_rh1);
            sts32(sA, rg);
            __syncthreads();
            #pragma unroll
            for (int c = 0; c < 8; c++) {
                if (c < 7) {
                    const float* nsrc = (c + 1 < 4) ? (g_rh1 + (c + 1) * KC * B_)
                                                    : (h0c + (c + 1 - 4) * KC * B_);
                    gather32(rg, nsrc);
                }
                float* buf = sA + (c & 1) * SABUF;
                mm1b(buf + b0 * SAROW, buf + b1 * SAROW, wh1p + c * KC, ph);
                if (c < 7) sts32(sA + ((c + 1) & 1) * SABUF, rg);
                __syncthreads();
            }
            float hta = tanhf(unpack_sum(ph[0]) + unpack_sum(ph[1]) + vbh1);
            float htb = tanhf(unpack_sum(ph[2]) + unpack_sum(ph[3]) + vbh1);
            float h1na = (1.f - z1a) * h1oa + z1a * hta;
            float h1nb = (1.f - z1b) * h1ob + z1b * htb;
            h1n[n * B_ + b0] = h1na;
            h1n[n * B_ + b1] = h1nb;
            int t1 = u - 1;
            g_H1[((size_t)t1 * B_ + b0) * H_ + n] = h1na;
            g_H1[((size_t)t1 * B_ + b1) * H_ + n] = h1nb;
        }
        grid_barrier();
        if (u > 0 && blockIdx.x == 0 && threadIdx.x == 0)
            atomicExch(&g_progress, u - 1);    // g_H1 rows t<=u-1 globally visible
    }
}

// ---------------- logits role: tile queue consumers ----------------
__device__ void logits_role(float* sm, const float* __restrict__ Wy,
                            const float* __restrict__ by, float* __restrict__ out) {
    float* As = sm;                 // [16][128]
    float* Bs = sm + 16 * 128;      // [16][128]
    int* s_idx = (int*)(sm + 32 * 128);
    int tid = threadIdx.x;
    int w = tid >> 5, l = tid & 31;
    int tx = (w & 1) * 8 + (l & 7);
    int ty = (w >> 1) * 4 + (l >> 3);
    const float* A = g_H1;

    while (true) {
        if (tid == 0) *s_idx = atomicAdd(&g_tile_ctr, 1);
        __syncthreads();
        int idx = *s_idx;
        __syncthreads();
        if (idx >= NTM * NTN) break;
        int mtile = idx / NTN, ntile = idx % NTN;
        int m0 = mtile * 128, n0 = ntile * 128;
        int need = mtile * 2 + 1;     // rows cover timesteps 2*mtile, 2*mtile+1
        if (tid == 0) {
            while (*((volatile int*)&g_progress) < need) { }
        }
        __syncthreads();
        __threadfence();

        unsigned long long acc2[8][4];
        #pragma unroll
        for (int i = 0; i < 8; i++)
            #pragma unroll
            for (int j = 0; j < 4; j++) acc2[i][j] = 0ull;

        for (int k0 = 0; k0 < H_; k0 += 16) {
            #pragma unroll
            for (int r = 0; r < 2; r++) {
                int f = tid + r * 256;
                int row = f >> 2, q = f & 3;
                float4 v = *(const float4*)&A[(size_t)(m0 + row) * H_ + k0 + q * 4];
                As[(q * 4 + 0) * 128 + row] = v.x; As[(q * 4 + 1) * 128 + row] = v.y;
                As[(q * 4 + 2) * 128 + row] = v.z; As[(q * 4 + 3) * 128 + row] = v.w;
            }
            #pragma unroll
            for (int r = 0; r < 2; r++) {
                int f = tid + r * 256;
                int row = f >> 2, q = f & 3;
                int nn = n0 + row;
                float4 v = make_float4(0.f, 0.f, 0.f, 0.f);
                if (nn < V_) v = *(const float4*)&Wy[(size_t)nn * H_ + k0 + q * 4];
                Bs[(q * 4 + 0) * 128 + row] = v.x; Bs[(q * 4 + 1) * 128 + row] = v.y;
                Bs[(q * 4 + 2) * 128 + row] = v.z; Bs[(q * 4 + 3) * 128 + row] = v.w;
            }
            __syncthreads();
            #pragma unroll
            for (int kk = 0; kk < 16; kk++) {
                float a[8];
                *(float4*)&a[0] = *(const float4*)&As[kk * 128 + ty * 4];
                *(float4*)&a[4] = *(const float4*)&As[kk * 128 + 64 + ty * 4];
                ulonglong2 bv0 = *(const ulonglong2*)&Bs[kk * 128 + tx * 4];
                ulonglong2 bv1 = *(const ulonglong2*)&Bs[kk * 128 + 64 + tx * 4];
                #pragma unroll
                for (int i = 0; i < 8; i++) {
                    unsigned long long ad = dup2(a[i]);
                    fma2(acc2[i][0], ad, bv0.x);
                    fma2(acc2[i][1], ad, bv0.y);
                    fma2(acc2[i][2], ad, bv1.x);
                    fma2(acc2[i][3], ad, bv1.y);
                }
            }
            __syncthreads();
        }
        #pragma unroll
        for (int i = 0; i < 8; i++) {
            int rloc = (i < 4) ? (ty * 4 + i) : (64 + ty * 4 + i - 4);
            size_t row = (size_t)m0 + rloc;
            #pragma unroll
            for (int jp = 0; jp < 4; jp++) {
                int v0 = n0 + ((jp < 2) ? (tx * 4 + jp * 2) : (64 + tx * 4 + (jp - 2) * 2));
                float lo = __uint_as_float((unsigned)acc2[i][jp]);
                float hi = __uint_as_float((unsigned)(acc2[i][jp] >> 32));
                if (v0 < V_)     out[row * V_ + v0]     = lo + by[v0];
                if (v0 + 1 < V_) out[row * V_ + v0 + 1] = hi + by[v0 + 1];
            }
        }
    }
}

// ---------------- fused kernel ----------------
__global__ void __launch_bounds__(TPB)
fused_kernel(const float* __restrict__ Wr0, const float* __restrict__ Wz0,
             const float* __restrict__ Wh0,
             const float* __restrict__ Wr1, const float* __restrict__ Wz1,
             const float* __restrict__ Wh1,
             const float* __restrict__ br1, const float* __restrict__ bz1,
             const float* __restrict__ bh1,
             const float* __restrict__ Wy, const float* __restrict__ by,
             float* __restrict__ out) {
    extern __shared__ float sm[];
    if (blockIdx.x < NB) {
        recurrence_role(sm, Wr0, Wz0, Wh0, Wr1, Wz1, Wh1, br1, bz1, bh1);
        __syncthreads();
    }
    logits_role(sm, Wy, by, out);
}

// ---------------- launch ----------------
extern "C" void kernel_launch(void* const* d_in, const int* in_sizes, int n_in,
                              void* d_out, int out_size) {
    const int*   inputs = (const int*)d_in[0];
    const float* hidden = (const float*)d_in[1];
    const float* emb    = (const float*)d_in[2];
    const float* W_r0 = (const float*)d_in[3];
    const float* b_r0 = (const float*)d_in[4];
    const float* W_z0 = (const float*)d_in[5];
    const float* b_z0 = (const float*)d_in[6];
    const float* W_h0 = (const float*)d_in[7];
    const float* b_h0 = (const float*)d_in[8];
    const float* W_r1 = (const float*)d_in[9];
    const float* b_r1 = (const float*)d_in[10];
    const float* W_z1 = (const float*)d_in[11];
    const float* b_z1 = (const float*)d_in[12];
    const float* W_h1 = (const float*)d_in[13];
    const float* b_h1 = (const float*)d_in[14];
    const float* Wy   = (const float*)d_in[15];
    const float* by   = (const float*)d_in[16];
    float* out = (float*)d_out;

    cudaFuncSetAttribute(fused_kernel, cudaFuncAttributeMaxDynamicSharedMemorySize,
                         SMEM_BYTES);

    xproj_gemm<<<dim3(3 * H_ / 128, (S_ * B_) / 128), 256>>>(inputs, emb, W_r0, W_z0, W_h0,
                                                             b_r0, b_z0, b_h0);
    init_hidden_kernel<<<(B_ * H_ + 255) / 256, 256>>>(hidden);
    fused_kernel<<<NCTA, TPB, SMEM_BYTES>>>(W_r0, W_z0, W_h0, W_r1, W_z1, W_h1,
                                            b_r1, b_z1, b_h1, Wy, by, out);

    long long logits_elems = (long long)S_ * B_ * V_;
    if ((long long)out_size >= logits_elems + 2LL * B_ * H_) {
        write_hidden_kernel<<<(B_ * H_ + 255) / 256, 256>>>(out, logits_elems);
    }
}